// round 1
// baseline (speedup 1.0000x reference)
#include <cuda_runtime.h>

#define NBATCH 32
#define HID 128
#define EMB 64
#define DEPTH 32
#define NODES 512
#define NPAR 8
#define ROWS_PER_B 16385          // output rows per batch (slot s -> row s-1)
#define PADK 132                  // padded leading dim for smem tiles (multiple of 4)
#define SMEM_BYTES (3 * 128 * PADK * 4)

// ---- device scratch (static: no allocation calls allowed) ----
__device__ float g_W1aT[128 * 128];          // W1[:, :128] transposed: [k][out]
__device__ float g_W1bT[64 * 128];           // W1[:, 128:192] transposed: [k][out]
__device__ float g_W2T[128 * 128];           // W2 transposed: [k][out]
__device__ float g_cpre[DEPTH * NODES * 128]; // per-node bias: W1b@ne + b1  (8MB)

// ---- packed f32x2 helpers ----
__device__ __forceinline__ unsigned long long pack2(float x, float y) {
    unsigned long long r;
    asm("mov.b64 %0, {%1, %2};" : "=l"(r) : "f"(x), "f"(y));
    return r;
}
__device__ __forceinline__ float2 unpack2(unsigned long long v) {
    float2 f;
    asm("mov.b64 {%0, %1}, %2;" : "=f"(f.x), "=f"(f.y) : "l"(v));
    return f;
}
__device__ __forceinline__ unsigned long long ffma2(unsigned long long a,
                                                    unsigned long long b,
                                                    unsigned long long c) {
    unsigned long long d;
    asm("fma.rn.f32x2 %0, %1, %2, %3;" : "=l"(d) : "l"(a), "l"(b), "l"(c));
    return d;
}

// 128x128x128 smem GEMM fragment: C[r0..r0+7][c0..c0+7] += A^T-tile * B-tile.
// A stored [k][row] (PADK stride), B stored [k][col] (PADK stride).
// acc[q][j] packs rows (r0+2q, r0+2q+1), col c0+j.
__device__ __forceinline__ void mm128(const float* __restrict__ A,
                                      const float* __restrict__ Bm,
                                      int r0, int c0,
                                      unsigned long long acc[4][8]) {
#pragma unroll 4
    for (int k = 0; k < 128; k++) {
        const float* ak = A + k * PADK + r0;
        ulonglong2 a01 = *(const ulonglong2*)(ak);      // rows r0..r0+3 (2 pairs)
        ulonglong2 a23 = *(const ulonglong2*)(ak + 4);  // rows r0+4..r0+7
        float4 bv0 = *(const float4*)(Bm + k * PADK + c0);
        float4 bv1 = *(const float4*)(Bm + k * PADK + c0 + 4);
        unsigned long long bb[8];
        bb[0] = pack2(bv0.x, bv0.x); bb[1] = pack2(bv0.y, bv0.y);
        bb[2] = pack2(bv0.z, bv0.z); bb[3] = pack2(bv0.w, bv0.w);
        bb[4] = pack2(bv1.x, bv1.x); bb[5] = pack2(bv1.y, bv1.y);
        bb[6] = pack2(bv1.z, bv1.z); bb[7] = pack2(bv1.w, bv1.w);
#pragma unroll
        for (int j = 0; j < 8; j++) {
            acc[0][j] = ffma2(a01.x, bb[j], acc[0][j]);
            acc[1][j] = ffma2(a01.y, bb[j], acc[1][j]);
            acc[2][j] = ffma2(a23.x, bb[j], acc[2][j]);
            acc[3][j] = ffma2(a23.y, bb[j], acc[3][j]);
        }
    }
}

// ---- init: weight transposes + root rows ----
__global__ void init_kernel(const float* __restrict__ emb,
                            const float* __restrict__ W1,
                            const float* __restrict__ W2,
                            float* __restrict__ out) {
    int bid = blockIdx.x, tid = threadIdx.x;  // grid 128, block 256; bid = output neuron
    for (int k = tid; k < 192; k += 256) {
        float v = W1[bid * 192 + k];
        if (k < 128) g_W1aT[k * 128 + bid] = v;
        else         g_W1bT[(k - 128) * 128 + bid] = v;
    }
    for (int k = tid; k < 128; k += 256)
        g_W2T[k * 128 + bid] = W2[bid * 128 + k];
    // root rows: out[b][0][:] = embedding[b][:]
    int g = bid * 256 + tid;
    if (g < NBATCH * HID) {
        int b = g >> 7, c = g & 127;
        out[(size_t)b * ROWS_PER_B * 128 + c] = emb[g];
    }
}

// ---- precompute c_pre = W1b @ ne + b1 for all D*N nodes ----
__global__ __launch_bounds__(256) void cpre_kernel(const float* __restrict__ emb_table,
                                                   const float* __restrict__ b1) {
    __shared__ float sne[32][64];
    __shared__ float sw[64][128];
    int tid = threadIdx.x;
    int row0 = blockIdx.x * 32;  // global node row = d*512 + n
    for (int i = tid; i < 32 * 64; i += 256) {
        int r = i >> 6, e = i & 63;
        sne[r][e] = emb_table[(size_t)(2 + row0 + r) * 64 + e];
    }
    for (int i = tid; i < 64 * 128; i += 256)
        sw[i >> 7][i & 127] = g_W1bT[i];
    __syncthreads();
    int c = tid & 127;
    int rh = (tid >> 7) * 16;
    float acc[16];
    float bv = b1[c];
#pragma unroll
    for (int rr = 0; rr < 16; rr++) acc[rr] = bv;
    for (int k = 0; k < 64; k++) {
        float w = sw[k][c];
#pragma unroll
        for (int rr = 0; rr < 16; rr++) acc[rr] += sne[rh + rr][k] * w;
    }
#pragma unroll
    for (int rr = 0; rr < 16; rr++)
        g_cpre[(size_t)(row0 + rh + rr) * 128 + c] = acc[rr];
}

// ---- per-depth kernel: gather + 2-layer MLP + residual ----
// Block: 256 threads, handles 4 nodes x 32 batches = 128 rows, all 128 cols.
// Grid: 128 blocks (NODES/4).
__global__ __launch_bounds__(256, 1)
void depth_kernel(float* __restrict__ out, const int* __restrict__ pidx,
                  const float* __restrict__ b2, int d) {
    extern __shared__ float sm[];
    float* As = sm;                   // pv transposed: [k][row]
    float* Bs = sm + 128 * PADK;      // weight tile: [k][col]
    float* Hs = sm + 2 * 128 * PADK;  // hidden transposed: [k][row]
    __shared__ int s_pidx[32];        // 4 nodes x 8 parents

    const int tid = threadIdx.x;
    const int n0 = blockIdx.x * 4;

    if (tid < 32)
        s_pidx[tid] = pidx[(d * NODES + n0 + (tid >> 3)) * NPAR + (tid & 7)];

    // Load Bs = W1aT
    {
        const float4* src = (const float4*)g_W1aT;
        for (int i = tid; i < 128 * 32; i += 256) {
            int k = i >> 5, c4 = i & 31;
            ((float4*)(Bs + k * PADK))[c4] = src[i];
        }
    }
    __syncthreads();

    // Gather: pv[row][:] = sum of parent vectors; store transposed into As.
    {
        const int warp = tid >> 5, lane = tid & 31;
#pragma unroll
        for (int rr = 0; rr < 16; rr++) {
            int r = warp * 16 + rr;
            int nn = r >> 5, b = r & 31;
            const float* base = out + (size_t)b * (ROWS_PER_B * 128);
            float x = 0.f, y = 0.f, z = 0.f, w = 0.f;
#pragma unroll
            for (int p = 0; p < NPAR; p++) {
                int s = s_pidx[nn * 8 + p];
                if (s) {
                    float4 v = *(const float4*)(base + (size_t)(s - 1) * 128 + lane * 4);
                    x += v.x; y += v.y; z += v.z; w += v.w;
                }
            }
            int k = lane * 4;
            As[(k + 0) * PADK + r] = x;
            As[(k + 1) * PADK + r] = y;
            As[(k + 2) * PADK + r] = z;
            As[(k + 3) * PADK + r] = w;
        }
    }
    __syncthreads();

    const int ty = tid >> 4, tx = tid & 15;
    const int r0 = ty * 8, c0 = tx * 8;
    const int nn = ty >> 2;  // all 8 rows of this thread share one node

    unsigned long long acc[4][8];

    // GEMM1: h = relu(pv @ W1a^T + c_pre[node])
    {
        const float* cp = g_cpre + (size_t)(d * NODES + n0 + nn) * 128 + c0;
        float4 cv0 = *(const float4*)cp;
        float4 cv1 = *(const float4*)(cp + 4);
        float cv[8] = {cv0.x, cv0.y, cv0.z, cv0.w, cv1.x, cv1.y, cv1.z, cv1.w};
#pragma unroll
        for (int q = 0; q < 4; q++)
#pragma unroll
            for (int j = 0; j < 8; j++)
                acc[q][j] = pack2(cv[j], cv[j]);
    }
    mm128(As, Bs, r0, c0, acc);

    // relu -> Hs (transposed [k][row]); safe: Hs untouched by concurrent GEMM1 readers
#pragma unroll
    for (int q = 0; q < 4; q++) {
#pragma unroll
        for (int j = 0; j < 8; j++) {
            float2 v = unpack2(acc[q][j]);
            v.x = fmaxf(v.x, 0.f);
            v.y = fmaxf(v.y, 0.f);
            *(unsigned long long*)(Hs + (c0 + j) * PADK + r0 + 2 * q) = pack2(v.x, v.y);
        }
    }
    __syncthreads();  // all done reading Bs(W1) and writing Hs

    // Reload Bs = W2T
    {
        const float4* src = (const float4*)g_W2T;
        for (int i = tid; i < 128 * 32; i += 256) {
            int k = i >> 5, c4 = i & 31;
            ((float4*)(Bs + k * PADK))[c4] = src[i];
        }
    }
    __syncthreads();

    // GEMM2: out = pv + h @ W2^T + b2 ; init acc with residual pv pairs from As
#pragma unroll
    for (int q = 0; q < 4; q++)
#pragma unroll
        for (int j = 0; j < 8; j++)
            acc[q][j] = *(const unsigned long long*)(As + (c0 + j) * PADK + r0 + 2 * q);
    mm128(Hs, Bs, r0, c0, acc);

    // Epilogue: add b2, write to out rows 1 + d*N + node
    {
        float4 bz0 = *(const float4*)(b2 + c0);
        float4 bz1 = *(const float4*)(b2 + c0 + 4);
        float bz[8] = {bz0.x, bz0.y, bz0.z, bz0.w, bz1.x, bz1.y, bz1.z, bz1.w};
        const int out_row = 1 + d * NODES + n0 + nn;
#pragma unroll
        for (int q = 0; q < 4; q++) {
            int r_a = r0 + 2 * q;
            int b_a = r_a & 31;
            float* pa = out + ((size_t)b_a * ROWS_PER_B + out_row) * 128 + c0;
            float* pb = out + ((size_t)(b_a + 1) * ROWS_PER_B + out_row) * 128 + c0;
            float2 v[8];
#pragma unroll
            for (int j = 0; j < 8; j++) v[j] = unpack2(acc[q][j]);
            float4 sa0 = make_float4(v[0].x + bz[0], v[1].x + bz[1], v[2].x + bz[2], v[3].x + bz[3]);
            float4 sa1 = make_float4(v[4].x + bz[4], v[5].x + bz[5], v[6].x + bz[6], v[7].x + bz[7]);
            float4 sb0 = make_float4(v[0].y + bz[0], v[1].y + bz[1], v[2].y + bz[2], v[3].y + bz[3]);
            float4 sb1 = make_float4(v[4].y + bz[4], v[5].y + bz[5], v[6].y + bz[6], v[7].y + bz[7]);
            *(float4*)pa = sa0;
            *(float4*)(pa + 4) = sa1;
            *(float4*)pb = sb0;
            *(float4*)(pb + 4) = sb1;
        }
    }
}

extern "C" void kernel_launch(void* const* d_in, const int* in_sizes, int n_in,
                              void* d_out, int out_size) {
    const float* embedding  = (const float*)d_in[0];
    const float* emb_table  = (const float*)d_in[1];
    const float* W1         = (const float*)d_in[2];
    const float* b1         = (const float*)d_in[3];
    const float* W2         = (const float*)d_in[4];
    const float* b2         = (const float*)d_in[5];
    const int*   parent_idx = (const int*)d_in[6];
    float* out = (float*)d_out;
    (void)in_sizes; (void)n_in; (void)out_size;

    cudaFuncSetAttribute(depth_kernel,
                         cudaFuncAttributeMaxDynamicSharedMemorySize, SMEM_BYTES);

    init_kernel<<<128, 256>>>(embedding, W1, W2, out);
    cpre_kernel<<<DEPTH * NODES / 32, 256>>>(emb_table, b1);
    for (int d = 0; d < DEPTH; d++)
        depth_kernel<<<NODES / 4, 256, SMEM_BYTES>>>(out, parent_idx, b2, d);
}

// round 4
// speedup vs baseline: 1.2069x; 1.2069x over previous
#include <cuda_runtime.h>
#include <cuda_bf16.h>
#include <cstdint>

#define DEPTH 32
#define NODES 512
#define NPAR 8
#define NB 32
#define HID 128
#define ROWS_PER_B 16385
#define STRB 272          // smem tile row stride in bytes (136 bf16)

// ---------------- device statics ----------------
__device__ float g_cpre[DEPTH * NODES * HID];   // W1b@ne + b1 per node (8MB)
__device__ float g_W1bT[64 * HID];
__device__ __nv_bfloat16 g_w1hi[HID * HID], g_w1lo[HID * HID];  // [n][k]
__device__ __nv_bfloat16 g_w2hi[HID * HID], g_w2lo[HID * HID];  // [n][k]
// node-major value mirror: g_buf[g_row][batch][128], g_row = slot-1
__device__ float g_buf[(size_t)(1 + DEPTH * NODES) * NB * HID];

// ---------------- helpers ----------------
__device__ __forceinline__ uint32_t smem_u32(const void* p) {
    uint32_t a;
    asm("{ .reg .u64 t; cvta.to.shared.u64 t, %1; cvt.u32.u64 %0, t; }" : "=r"(a) : "l"(p));
    return a;
}
__device__ __forceinline__ void ldsm4(uint32_t addr, uint32_t r[4]) {
    asm volatile("ldmatrix.sync.aligned.m8n8.x4.shared.b16 {%0,%1,%2,%3}, [%4];"
        : "=r"(r[0]), "=r"(r[1]), "=r"(r[2]), "=r"(r[3]) : "r"(addr));
}
__device__ __forceinline__ void mma16816(float c[4], const uint32_t a[4],
                                         uint32_t b0, uint32_t b1) {
    asm volatile("mma.sync.aligned.m16n8k16.row.col.f32.bf16.bf16.f32 "
        "{%0,%1,%2,%3}, {%4,%5,%6,%7}, {%8,%9}, {%0,%1,%2,%3};"
        : "+f"(c[0]), "+f"(c[1]), "+f"(c[2]), "+f"(c[3])
        : "r"(a[0]), "r"(a[1]), "r"(a[2]), "r"(a[3]), "r"(b0), "r"(b1));
}
// fp32 pair -> bf16 hi word + bf16 lo word (first elem in low half)
__device__ __forceinline__ void split2(float a, float b, uint32_t& hi, uint32_t& lo) {
    __nv_bfloat16 ah = __float2bfloat16(a), bh = __float2bfloat16(b);
    __nv_bfloat16 al = __float2bfloat16(a - __bfloat162float(ah));
    __nv_bfloat16 bl = __float2bfloat16(b - __bfloat162float(bh));
    hi = (uint32_t)__bfloat16_as_ushort(ah) | ((uint32_t)__bfloat16_as_ushort(bh) << 16);
    lo = (uint32_t)__bfloat16_as_ushort(al) | ((uint32_t)__bfloat16_as_ushort(bl) << 16);
}

// ---------------- smem layout ----------------
#define SM_PIDX 0
#define SM_CPRE 512
#define SM_B2   2560
#define SM_AHI  3072
#define TILE_B  (128 * STRB)          // 34816
#define SM_ALO  (SM_AHI + TILE_B)
#define SM_W1HI (SM_ALO + TILE_B)
#define SM_W1LO (SM_W1HI + TILE_B)
#define SM_W2HI (SM_W1LO + TILE_B)
#define SM_W2LO (SM_W2HI + TILE_B)
#define SMEM_TOTAL (SM_W2LO + TILE_B) // 211968

// single split-term: acc += A(Abase) * B(Bbase), K=128
__device__ __forceinline__ void gemm_term(uint32_t Abase, uint32_t Bbase,
                                          int r0, int c0, int lane,
                                          float acc[2][8][4]) {
    const uint32_t rsel = (uint32_t)(lane & 15);
    const uint32_t ksel = (uint32_t)(lane >> 4) * 16;
    uint32_t aRow0 = Abase + (r0 + rsel) * STRB + ksel;
    uint32_t aRow1 = Abase + (r0 + 16 + rsel) * STRB + ksel;
    uint32_t bRow  = Bbase + (c0 + rsel) * STRB + ksel;
#pragma unroll
    for (int kc = 0; kc < 8; kc++) {
        uint32_t kb = kc * 32;
        uint32_t a[2][4];
        ldsm4(aRow0 + kb, a[0]);
        ldsm4(aRow1 + kb, a[1]);
        uint32_t b[4][4];
#pragma unroll
        for (int nt = 0; nt < 4; nt++)
            ldsm4(bRow + nt * 16 * STRB + kb, b[nt]);
#pragma unroll
        for (int mt = 0; mt < 2; mt++)
#pragma unroll
            for (int nt = 0; nt < 4; nt++) {
                mma16816(acc[mt][nt * 2 + 0], a[mt], b[nt][0], b[nt][2]);
                mma16816(acc[mt][nt * 2 + 1], a[mt], b[nt][1], b[nt][3]);
            }
    }
}

// ---------------- prep ----------------
__global__ void prep_kernel(const float* __restrict__ emb,
                            const float* __restrict__ W1,
                            const float* __restrict__ W2,
                            float* __restrict__ out) {
    int n = blockIdx.x, tid = threadIdx.x;  // 128 x 256
    for (int k = tid; k < 192; k += 256) {
        float v = W1[n * 192 + k];
        if (k < 128) {
            __nv_bfloat16 h = __float2bfloat16(v);
            g_w1hi[n * HID + k] = h;
            g_w1lo[n * HID + k] = __float2bfloat16(v - __bfloat162float(h));
        } else {
            g_W1bT[(k - 128) * HID + n] = v;
        }
    }
    for (int k = tid; k < 128; k += 256) {
        float v = W2[n * HID + k];
        __nv_bfloat16 h = __float2bfloat16(v);
        g_w2hi[n * HID + k] = h;
        g_w2lo[n * HID + k] = __float2bfloat16(v - __bfloat162float(h));
    }
    int g = n * 256 + tid;
    if (g < NB * HID) {
        int b = g >> 7, c = g & 127;
        out[(size_t)b * ROWS_PER_B * HID + c] = emb[g];
        g_buf[(size_t)b * HID + c] = emb[g];
    }
}

// ---------------- c_pre = W1b @ ne + b1 ----------------
__global__ __launch_bounds__(256) void cpre_kernel(const float* __restrict__ emb_table,
                                                   const float* __restrict__ b1) {
    __shared__ float sne[32][64];
    __shared__ float sw[64][128];
    int tid = threadIdx.x;
    int row0 = blockIdx.x * 32;
    for (int i = tid; i < 32 * 64; i += 256) {
        int r = i >> 6, e = i & 63;
        sne[r][e] = emb_table[(size_t)(2 + row0 + r) * 64 + e];
    }
    for (int i = tid; i < 64 * 128; i += 256)
        sw[i >> 7][i & 127] = g_W1bT[i];
    __syncthreads();
    int c = tid & 127;
    int rh = (tid >> 7) * 16;
    float acc[16];
    float bv = b1[c];
#pragma unroll
    for (int rr = 0; rr < 16; rr++) acc[rr] = bv;
    for (int k = 0; k < 64; k++) {
        float w = sw[k][c];
#pragma unroll
        for (int rr = 0; rr < 16; rr++) acc[rr] += sne[rh + rr][k] * w;
    }
#pragma unroll
    for (int rr = 0; rr < 16; rr++)
        g_cpre[(size_t)(row0 + rh + rr) * HID + c] = acc[rr];
}

// ---------------- per-depth kernel ----------------
__global__ __launch_bounds__(256, 1)
void depth_kernel(float* __restrict__ out, const int* __restrict__ pidx,
                  const float* __restrict__ b2, int d) {
    extern __shared__ char smc[];
    const uint32_t sb = smem_u32(smc);
    const int tid = threadIdx.x;
    const int wid = tid >> 5, lane = tid & 31;
    const int n0 = blockIdx.x * 4;

    if (tid < 32)
        ((int*)(smc + SM_PIDX))[tid] = pidx[(d * NODES + n0 + (tid >> 3)) * NPAR + (tid & 7)];
    {
        float* s_cpre = (float*)(smc + SM_CPRE);
        const float* gc = g_cpre + (size_t)(d * NODES + n0) * HID;
        for (int i = tid; i < 512; i += 256) s_cpre[i] = gc[i];
        float* s_b2 = (float*)(smc + SM_B2);
        for (int i = tid; i < 128; i += 256) s_b2[i] = b2[i];
    }
    // weights -> smem (uint2 = 4 bf16), row stride 272B
    {
        const uint2* w1h = (const uint2*)g_w1hi;
        const uint2* w1l = (const uint2*)g_w1lo;
        const uint2* w2h = (const uint2*)g_w2hi;
        const uint2* w2l = (const uint2*)g_w2lo;
        for (int i = tid; i < 128 * 32; i += 256) {
            int r = i >> 5, q = i & 31;
            uint32_t off = (uint32_t)r * STRB + q * 8;
            *(uint2*)(smc + SM_W1HI + off) = w1h[i];
            *(uint2*)(smc + SM_W1LO + off) = w1l[i];
            *(uint2*)(smc + SM_W2HI + off) = w2h[i];
            *(uint2*)(smc + SM_W2LO + off) = w2l[i];
        }
    }

    // ---- gather: pv = sum parents; pv -> out row (f32); bf16 split -> A tiles ----
    {
        const int* s_pidx = (const int*)(smc + SM_PIDX);
        __syncthreads();  // s_pidx ready (weights done too)
#pragma unroll 4
        for (int rr = 0; rr < 16; rr++) {
            int r = wid * 16 + rr;
            int nn = r >> 5, b = r & 31;
            float x = 0.f, y = 0.f, z = 0.f, w = 0.f;
#pragma unroll
            for (int p = 0; p < NPAR; p++) {
                int s = s_pidx[nn * 8 + p];
                if (s) {
                    const float* src = g_buf + ((size_t)(s - 1) * NB + b) * HID + lane * 4;
                    float4 v = *(const float4*)src;
                    x += v.x; y += v.y; z += v.z; w += v.w;
                }
            }
            int orow = 1 + d * NODES + n0 + nn;
            *(float4*)(out + ((size_t)b * ROWS_PER_B + orow) * HID + lane * 4) =
                make_float4(x, y, z, w);
            uint32_t h0, l0, h1, l1;
            split2(x, y, h0, l0);
            split2(z, w, h1, l1);
            uint32_t o = (uint32_t)r * STRB + lane * 8;
            *(uint32_t*)(smc + SM_AHI + o) = h0;
            *(uint32_t*)(smc + SM_AHI + o + 4) = h1;
            *(uint32_t*)(smc + SM_ALO + o) = l0;
            *(uint32_t*)(smc + SM_ALO + o + 4) = l1;
        }
    }
    __syncthreads();

    const int r0 = (wid & 3) * 32;    // warp row base (single node per warp)
    const int c0 = (wid >> 2) * 64;   // warp col base
    const int nn = wid & 3;
    const int tq = lane >> 2;         // row within 8
    const int tc = (lane & 3) * 2;    // col pair base
    const float* s_cpre = (const float*)(smc + SM_CPRE);
    const float* s_b2 = (const float*)(smc + SM_B2);

    float acc[2][8][4];
#pragma unroll
    for (int mt = 0; mt < 2; mt++)
#pragma unroll
        for (int nt = 0; nt < 8; nt++)
#pragma unroll
            for (int q = 0; q < 4; q++) acc[mt][nt][q] = 0.f;

    // ---- GEMM1: Xhi*W1hi + Xlo*W1hi + Xhi*W1lo ----
    gemm_term(sb + SM_AHI, sb + SM_W1HI, r0, c0, lane, acc);
    gemm_term(sb + SM_ALO, sb + SM_W1HI, r0, c0, lane, acc);
    gemm_term(sb + SM_AHI, sb + SM_W1LO, r0, c0, lane, acc);

    __syncthreads();  // all warps done reading A tiles

    // ---- relu(D1 + cpre) -> split -> H into A tiles ----
#pragma unroll
    for (int mt = 0; mt < 2; mt++) {
#pragma unroll
        for (int nt = 0; nt < 8; nt++) {
            int c = c0 + nt * 8 + tc;
            float cp0 = s_cpre[nn * HID + c], cp1 = s_cpre[nn * HID + c + 1];
            float v0 = fmaxf(acc[mt][nt][0] + cp0, 0.f);
            float v1 = fmaxf(acc[mt][nt][1] + cp1, 0.f);
            float v2 = fmaxf(acc[mt][nt][2] + cp0, 0.f);
            float v3 = fmaxf(acc[mt][nt][3] + cp1, 0.f);
            uint32_t hi, lo;
            uint32_t oA = (uint32_t)(r0 + mt * 16 + tq) * STRB + c * 2;
            uint32_t oB = oA + 8 * STRB;
            split2(v0, v1, hi, lo);
            *(uint32_t*)(smc + SM_AHI + oA) = hi;
            *(uint32_t*)(smc + SM_ALO + oA) = lo;
            split2(v2, v3, hi, lo);
            *(uint32_t*)(smc + SM_AHI + oB) = hi;
            *(uint32_t*)(smc + SM_ALO + oB) = lo;
        }
    }
    __syncthreads();

#pragma unroll
    for (int mt = 0; mt < 2; mt++)
#pragma unroll
        for (int nt = 0; nt < 8; nt++)
#pragma unroll
            for (int q = 0; q < 4; q++) acc[mt][nt][q] = 0.f;

    // ---- GEMM2: Hhi*W2hi + Hlo*W2hi + Hhi*W2lo ----
    gemm_term(sb + SM_AHI, sb + SM_W2HI, r0, c0, lane, acc);
    gemm_term(sb + SM_ALO, sb + SM_W2HI, r0, c0, lane, acc);
    gemm_term(sb + SM_AHI, sb + SM_W2LO, r0, c0, lane, acc);

    // ---- epilogue: out = pv + D2 + b2 ; mirror to g_buf (same row as out!) ----
    {
        const int orow = 1 + d * NODES + n0 + nn;   // out row AND g_buf row (slot-1)
#pragma unroll
        for (int mt = 0; mt < 2; mt++) {
#pragma unroll
            for (int half = 0; half < 2; half++) {
                int b = mt * 16 + tq + half * 8;  // batch index (r - r0)
                float* po = out + ((size_t)b * ROWS_PER_B + orow) * HID;
                float* pg = g_buf + ((size_t)orow * NB + b) * HID;
#pragma unroll
                for (int nt = 0; nt < 8; nt++) {
                    int c = c0 + nt * 8 + tc;
                    float2 pv = *(const float2*)(po + c);
                    float2 o;
                    o.x = acc[mt][nt][half * 2 + 0] + s_b2[c] + pv.x;
                    o.y = acc[mt][nt][half * 2 + 1] + s_b2[c + 1] + pv.y;
                    *(float2*)(po + c) = o;
                    *(float2*)(pg + c) = o;
                }
            }
        }
    }
}

extern "C" void kernel_launch(void* const* d_in, const int* in_sizes, int n_in,
                              void* d_out, int out_size) {
    const float* embedding  = (const float*)d_in[0];
    const float* emb_table  = (const float*)d_in[1];
    const float* W1         = (const float*)d_in[2];
    const float* b1         = (const float*)d_in[3];
    const float* W2         = (const float*)d_in[4];
    const float* b2         = (const float*)d_in[5];
    const int*   parent_idx = (const int*)d_in[6];
    float* out = (float*)d_out;
    (void)in_sizes; (void)n_in; (void)out_size;

    cudaFuncSetAttribute(depth_kernel,
                         cudaFuncAttributeMaxDynamicSharedMemorySize, SMEM_TOTAL);

    prep_kernel<<<128, 256>>>(embedding, W1, W2, out);
    cpre_kernel<<<DEPTH * NODES / 32, 256>>>(emb_table, b1);
    for (int d = 0; d < DEPTH; d++)
        depth_kernel<<<128, 256, SMEM_TOTAL>>>(out, parent_idx, b2, d);
}

// round 5
// speedup vs baseline: 1.3348x; 1.1059x over previous
#include <cuda_runtime.h>
#include <cuda_bf16.h>
#include <cstdint>

#define DEPTH 32
#define NODES 512
#define NPAR 8
#define NB 32
#define HID 128
#define ROWS_PER_B 16385
#define STRB 272          // smem tile row stride in bytes (136 bf16)
#define NTHREADS 512

// ---------------- device statics ----------------
__device__ float g_cpre[DEPTH * NODES * HID];   // W1b@ne + b1 per node (8MB)
__device__ float g_W1bT[64 * HID];
__device__ __nv_bfloat16 g_w1hi[HID * HID], g_w1lo[HID * HID];  // [n][k]
__device__ __nv_bfloat16 g_w2hi[HID * HID], g_w2lo[HID * HID];  // [n][k]
// node-major value mirror: g_buf[g_row][batch][128], g_row = slot-1
__device__ float g_buf[(size_t)(1 + DEPTH * NODES) * NB * HID];

// ---------------- helpers ----------------
__device__ __forceinline__ uint32_t smem_u32(const void* p) {
    uint32_t a;
    asm("{ .reg .u64 t; cvta.to.shared.u64 t, %1; cvt.u32.u64 %0, t; }" : "=r"(a) : "l"(p));
    return a;
}
__device__ __forceinline__ void ldsm4(uint32_t addr, uint32_t r[4]) {
    asm volatile("ldmatrix.sync.aligned.m8n8.x4.shared.b16 {%0,%1,%2,%3}, [%4];"
        : "=r"(r[0]), "=r"(r[1]), "=r"(r[2]), "=r"(r[3]) : "r"(addr));
}
__device__ __forceinline__ void mma16816(float c[4], const uint32_t a[4],
                                         uint32_t b0, uint32_t b1) {
    asm volatile("mma.sync.aligned.m16n8k16.row.col.f32.bf16.bf16.f32 "
        "{%0,%1,%2,%3}, {%4,%5,%6,%7}, {%8,%9}, {%0,%1,%2,%3};"
        : "+f"(c[0]), "+f"(c[1]), "+f"(c[2]), "+f"(c[3])
        : "r"(a[0]), "r"(a[1]), "r"(a[2]), "r"(a[3]), "r"(b0), "r"(b1));
}
// fp32 pair -> bf16 hi word + bf16 lo word (first elem in low half)
__device__ __forceinline__ void split2(float a, float b, uint32_t& hi, uint32_t& lo) {
    __nv_bfloat16 ah = __float2bfloat16(a), bh = __float2bfloat16(b);
    __nv_bfloat16 al = __float2bfloat16(a - __bfloat162float(ah));
    __nv_bfloat16 bl = __float2bfloat16(b - __bfloat162float(bh));
    hi = (uint32_t)__bfloat16_as_ushort(ah) | ((uint32_t)__bfloat16_as_ushort(bh) << 16);
    lo = (uint32_t)__bfloat16_as_ushort(al) | ((uint32_t)__bfloat16_as_ushort(bl) << 16);
}

// ---------------- smem layout ----------------
#define SM_PIDX 0
#define SM_CPRE 512
#define SM_B2   2560
#define SM_AHI  3072
#define TILE_B  (128 * STRB)          // 34816
#define SM_ALO  (SM_AHI + TILE_B)
#define SM_W1HI (SM_ALO + TILE_B)
#define SM_W1LO (SM_W1HI + TILE_B)
#define SM_W2HI (SM_W1LO + TILE_B)
#define SM_W2LO (SM_W2HI + TILE_B)
#define SMEM_TOTAL (SM_W2LO + TILE_B) // 211968

// single split-term for a 32x32 warp tile: acc += A * B, K=128
__device__ __forceinline__ void gemm_term(uint32_t Abase, uint32_t Bbase,
                                          int r0, int c0, int lane,
                                          float acc[2][4][4]) {
    const uint32_t rsel = (uint32_t)(lane & 15);
    const uint32_t ksel = (uint32_t)(lane >> 4) * 16;
    uint32_t aRow0 = Abase + (r0 + rsel) * STRB + ksel;
    uint32_t aRow1 = aRow0 + 16 * STRB;
    uint32_t bRow0 = Bbase + (c0 + rsel) * STRB + ksel;
    uint32_t bRow1 = bRow0 + 16 * STRB;
#pragma unroll
    for (int kc = 0; kc < 8; kc++) {
        uint32_t kb = kc * 32;
        uint32_t a0[4], a1[4], b0[4], b1[4];
        ldsm4(aRow0 + kb, a0);
        ldsm4(aRow1 + kb, a1);
        ldsm4(bRow0 + kb, b0);
        ldsm4(bRow1 + kb, b1);
        mma16816(acc[0][0], a0, b0[0], b0[2]);
        mma16816(acc[0][1], a0, b0[1], b0[3]);
        mma16816(acc[0][2], a0, b1[0], b1[2]);
        mma16816(acc[0][3], a0, b1[1], b1[3]);
        mma16816(acc[1][0], a1, b0[0], b0[2]);
        mma16816(acc[1][1], a1, b0[1], b0[3]);
        mma16816(acc[1][2], a1, b1[0], b1[2]);
        mma16816(acc[1][3], a1, b1[1], b1[3]);
    }
}

// ---------------- prep ----------------
__global__ void prep_kernel(const float* __restrict__ emb,
                            const float* __restrict__ W1,
                            const float* __restrict__ W2,
                            float* __restrict__ out) {
    int n = blockIdx.x, tid = threadIdx.x;  // 128 x 256
    for (int k = tid; k < 192; k += 256) {
        float v = W1[n * 192 + k];
        if (k < 128) {
            __nv_bfloat16 h = __float2bfloat16(v);
            g_w1hi[n * HID + k] = h;
            g_w1lo[n * HID + k] = __float2bfloat16(v - __bfloat162float(h));
        } else {
            g_W1bT[(k - 128) * HID + n] = v;
        }
    }
    for (int k = tid; k < 128; k += 256) {
        float v = W2[n * HID + k];
        __nv_bfloat16 h = __float2bfloat16(v);
        g_w2hi[n * HID + k] = h;
        g_w2lo[n * HID + k] = __float2bfloat16(v - __bfloat162float(h));
    }
    int g = n * 256 + tid;
    if (g < NB * HID) {
        int b = g >> 7, c = g & 127;
        out[(size_t)b * ROWS_PER_B * HID + c] = emb[g];
        g_buf[(size_t)b * HID + c] = emb[g];
    }
}

// ---------------- c_pre = W1b @ ne + b1 ----------------
__global__ __launch_bounds__(256) void cpre_kernel(const float* __restrict__ emb_table,
                                                   const float* __restrict__ b1) {
    __shared__ float sne[32][64];
    __shared__ float sw[64][128];
    int tid = threadIdx.x;
    int row0 = blockIdx.x * 32;
    for (int i = tid; i < 32 * 64; i += 256) {
        int r = i >> 6, e = i & 63;
        sne[r][e] = emb_table[(size_t)(2 + row0 + r) * 64 + e];
    }
    for (int i = tid; i < 64 * 128; i += 256)
        sw[i >> 7][i & 127] = g_W1bT[i];
    __syncthreads();
    int c = tid & 127;
    int rh = (tid >> 7) * 16;
    float acc[16];
    float bv = b1[c];
#pragma unroll
    for (int rr = 0; rr < 16; rr++) acc[rr] = bv;
    for (int k = 0; k < 64; k++) {
        float w = sw[k][c];
#pragma unroll
        for (int rr = 0; rr < 16; rr++) acc[rr] += sne[rh + rr][k] * w;
    }
#pragma unroll
    for (int rr = 0; rr < 16; rr++)
        g_cpre[(size_t)(row0 + rh + rr) * HID + c] = acc[rr];
}

// ---------------- per-depth kernel: 512 threads, 16 warps, 32x32 warp tiles ----------------
__global__ __launch_bounds__(NTHREADS, 1)
void depth_kernel(float* __restrict__ out, const int* __restrict__ pidx,
                  const float* __restrict__ b2, int d) {
    extern __shared__ char smc[];
    const uint32_t sb = smem_u32(smc);
    const int tid = threadIdx.x;
    const int wid = tid >> 5, lane = tid & 31;
    const int n0 = blockIdx.x * 4;

    if (tid < 32)
        ((int*)(smc + SM_PIDX))[tid] = pidx[(d * NODES + n0 + (tid >> 3)) * NPAR + (tid & 7)];
    {
        float* s_cpre = (float*)(smc + SM_CPRE);
        const float* gc = g_cpre + (size_t)(d * NODES + n0) * HID;
        for (int i = tid; i < 512; i += NTHREADS) s_cpre[i] = gc[i];
        float* s_b2 = (float*)(smc + SM_B2);
        if (tid < 128) s_b2[tid] = b2[tid];
    }
    // weights -> smem (uint2 = 4 bf16), row stride 272B
    {
        const uint2* w1h = (const uint2*)g_w1hi;
        const uint2* w1l = (const uint2*)g_w1lo;
        const uint2* w2h = (const uint2*)g_w2hi;
        const uint2* w2l = (const uint2*)g_w2lo;
        for (int i = tid; i < 128 * 32; i += NTHREADS) {
            int r = i >> 5, q = i & 31;
            uint32_t off = (uint32_t)r * STRB + q * 8;
            *(uint2*)(smc + SM_W1HI + off) = w1h[i];
            *(uint2*)(smc + SM_W1LO + off) = w1l[i];
            *(uint2*)(smc + SM_W2HI + off) = w2h[i];
            *(uint2*)(smc + SM_W2LO + off) = w2l[i];
        }
    }

    // ---- gather: pv = sum parents; pv -> out row (f32); bf16 split -> A tiles ----
    {
        const int* s_pidx = (const int*)(smc + SM_PIDX);
        __syncthreads();  // s_pidx ready
#pragma unroll
        for (int rr = 0; rr < 8; rr++) {
            int r = wid * 8 + rr;
            int nn = r >> 5, b = r & 31;
            float x = 0.f, y = 0.f, z = 0.f, w = 0.f;
#pragma unroll
            for (int p = 0; p < NPAR; p++) {
                int s = s_pidx[nn * 8 + p];
                if (s) {
                    const float* src = g_buf + ((size_t)(s - 1) * NB + b) * HID + lane * 4;
                    float4 v = *(const float4*)src;
                    x += v.x; y += v.y; z += v.z; w += v.w;
                }
            }
            int orow = 1 + d * NODES + n0 + nn;
            *(float4*)(out + ((size_t)b * ROWS_PER_B + orow) * HID + lane * 4) =
                make_float4(x, y, z, w);
            uint32_t h0, l0, h1, l1;
            split2(x, y, h0, l0);
            split2(z, w, h1, l1);
            uint32_t o = (uint32_t)r * STRB + lane * 8;
            *(uint32_t*)(smc + SM_AHI + o) = h0;
            *(uint32_t*)(smc + SM_AHI + o + 4) = h1;
            *(uint32_t*)(smc + SM_ALO + o) = l0;
            *(uint32_t*)(smc + SM_ALO + o + 4) = l1;
        }
    }
    __syncthreads();

    const int nn = wid & 3;           // node index = row group
    const int r0 = nn * 32;           // warp row base
    const int c0 = (wid >> 2) * 32;   // warp col base
    const int tq = lane >> 2;         // row within 8
    const int tc = (lane & 3) * 2;    // col pair base
    const float* s_cpre = (const float*)(smc + SM_CPRE);
    const float* s_b2 = (const float*)(smc + SM_B2);

    float acc[2][4][4];
#pragma unroll
    for (int mt = 0; mt < 2; mt++)
#pragma unroll
        for (int nt = 0; nt < 4; nt++)
#pragma unroll
            for (int q = 0; q < 4; q++) acc[mt][nt][q] = 0.f;

    // ---- GEMM1: Xhi*W1hi + Xlo*W1hi + Xhi*W1lo ----
    gemm_term(sb + SM_AHI, sb + SM_W1HI, r0, c0, lane, acc);
    gemm_term(sb + SM_ALO, sb + SM_W1HI, r0, c0, lane, acc);
    gemm_term(sb + SM_AHI, sb + SM_W1LO, r0, c0, lane, acc);

    __syncthreads();  // all warps done reading A tiles

    // ---- relu(D1 + cpre) -> split -> H into A tiles ----
#pragma unroll
    for (int mt = 0; mt < 2; mt++) {
#pragma unroll
        for (int nt = 0; nt < 4; nt++) {
            int c = c0 + nt * 8 + tc;
            float cp0 = s_cpre[nn * HID + c], cp1 = s_cpre[nn * HID + c + 1];
            float v0 = fmaxf(acc[mt][nt][0] + cp0, 0.f);
            float v1 = fmaxf(acc[mt][nt][1] + cp1, 0.f);
            float v2 = fmaxf(acc[mt][nt][2] + cp0, 0.f);
            float v3 = fmaxf(acc[mt][nt][3] + cp1, 0.f);
            uint32_t hi, lo;
            uint32_t oA = (uint32_t)(r0 + mt * 16 + tq) * STRB + c * 2;
            uint32_t oB = oA + 8 * STRB;
            split2(v0, v1, hi, lo);
            *(uint32_t*)(smc + SM_AHI + oA) = hi;
            *(uint32_t*)(smc + SM_ALO + oA) = lo;
            split2(v2, v3, hi, lo);
            *(uint32_t*)(smc + SM_AHI + oB) = hi;
            *(uint32_t*)(smc + SM_ALO + oB) = lo;
        }
    }
    __syncthreads();

#pragma unroll
    for (int mt = 0; mt < 2; mt++)
#pragma unroll
        for (int nt = 0; nt < 4; nt++)
#pragma unroll
            for (int q = 0; q < 4; q++) acc[mt][nt][q] = 0.f;

    // ---- GEMM2: Hhi*W2hi + Hlo*W2hi + Hhi*W2lo ----
    gemm_term(sb + SM_AHI, sb + SM_W2HI, r0, c0, lane, acc);
    gemm_term(sb + SM_ALO, sb + SM_W2HI, r0, c0, lane, acc);
    gemm_term(sb + SM_AHI, sb + SM_W2LO, r0, c0, lane, acc);

    // ---- epilogue: out = pv + D2 + b2 ; mirror to g_buf (same row as out) ----
    {
        const int orow = 1 + d * NODES + n0 + nn;   // out row AND g_buf row (slot-1)
#pragma unroll
        for (int mt = 0; mt < 2; mt++) {
#pragma unroll
            for (int half = 0; half < 2; half++) {
                int b = mt * 16 + tq + half * 8;  // batch index (r - r0)
                float* po = out + ((size_t)b * ROWS_PER_B + orow) * HID;
                float* pg = g_buf + ((size_t)orow * NB + b) * HID;
#pragma unroll
                for (int nt = 0; nt < 4; nt++) {
                    int c = c0 + nt * 8 + tc;
                    float2 pv = *(const float2*)(po + c);
                    float2 o;
                    o.x = acc[mt][nt][half * 2 + 0] + s_b2[c] + pv.x;
                    o.y = acc[mt][nt][half * 2 + 1] + s_b2[c + 1] + pv.y;
                    *(float2*)(po + c) = o;
                    *(float2*)(pg + c) = o;
                }
            }
        }
    }
}

extern "C" void kernel_launch(void* const* d_in, const int* in_sizes, int n_in,
                              void* d_out, int out_size) {
    const float* embedding  = (const float*)d_in[0];
    const float* emb_table  = (const float*)d_in[1];
    const float* W1         = (const float*)d_in[2];
    const float* b1         = (const float*)d_in[3];
    const float* W2         = (const float*)d_in[4];
    const float* b2         = (const float*)d_in[5];
    const int*   parent_idx = (const int*)d_in[6];
    float* out = (float*)d_out;
    (void)in_sizes; (void)n_in; (void)out_size;

    cudaFuncSetAttribute(depth_kernel,
                         cudaFuncAttributeMaxDynamicSharedMemorySize, SMEM_TOTAL);

    prep_kernel<<<128, 256>>>(embedding, W1, W2, out);
    cpre_kernel<<<DEPTH * NODES / 32, 256>>>(emb_table, b1);
    for (int d = 0; d < DEPTH; d++)
        depth_kernel<<<128, NTHREADS, SMEM_TOTAL>>>(out, parent_idx, b2, d);
}

// round 6
// speedup vs baseline: 1.4999x; 1.1237x over previous
#include <cuda_runtime.h>
#include <cuda_bf16.h>
#include <cstdint>

#define DEPTH 32
#define NODES 512
#define NPAR 8
#define NB 32
#define HID 128
#define ROWS_PER_B 16385
#define STRB 272            // smem tile row stride bytes (136 bf16)
#define NTHREADS 512
#define ZROW 16385          // permanent zero row of g_buf (slot 0 padding)

// ---------------- device statics ----------------
__device__ float g_cpre[DEPTH * NODES * HID];
__device__ float g_W1bT[64 * HID];
__device__ __nv_bfloat16 g_w1hi[HID * HID], g_w1lo[HID * HID];  // [n][k]
__device__ __nv_bfloat16 g_w2hi[HID * HID], g_w2lo[HID * HID];  // [n][k]
// node-major value mirror + 1 zero row: g_buf[g_row][batch][128], g_row = slot-1
__device__ float g_buf[(size_t)(2 + DEPTH * NODES) * NB * HID];
// grid barrier state (restored to 0 after 32 (even) barriers per run)
__device__ unsigned g_cnt;
__device__ volatile unsigned g_sense;

// ---------------- helpers ----------------
__device__ __forceinline__ uint32_t smem_u32(const void* p) {
    uint32_t a;
    asm("{ .reg .u64 t; cvta.to.shared.u64 t, %1; cvt.u32.u64 %0, t; }" : "=r"(a) : "l"(p));
    return a;
}
__device__ __forceinline__ void ldsm4(uint32_t addr, uint32_t r[4]) {
    asm volatile("ldmatrix.sync.aligned.m8n8.x4.shared.b16 {%0,%1,%2,%3}, [%4];"
        : "=r"(r[0]), "=r"(r[1]), "=r"(r[2]), "=r"(r[3]) : "r"(addr));
}
__device__ __forceinline__ void mma16816(float c[4], const uint32_t a[4],
                                         uint32_t b0, uint32_t b1) {
    asm volatile("mma.sync.aligned.m16n8k16.row.col.f32.bf16.bf16.f32 "
        "{%0,%1,%2,%3}, {%4,%5,%6,%7}, {%8,%9}, {%0,%1,%2,%3};"
        : "+f"(c[0]), "+f"(c[1]), "+f"(c[2]), "+f"(c[3])
        : "r"(a[0]), "r"(a[1]), "r"(a[2]), "r"(a[3]), "r"(b0), "r"(b1));
}
__device__ __forceinline__ void split2(float a, float b, uint32_t& hi, uint32_t& lo) {
    __nv_bfloat16 ah = __float2bfloat16(a), bh = __float2bfloat16(b);
    __nv_bfloat16 al = __float2bfloat16(a - __bfloat162float(ah));
    __nv_bfloat16 bl = __float2bfloat16(b - __bfloat162float(bh));
    hi = (uint32_t)__bfloat16_as_ushort(ah) | ((uint32_t)__bfloat16_as_ushort(bh) << 16);
    lo = (uint32_t)__bfloat16_as_ushort(al) | ((uint32_t)__bfloat16_as_ushort(bl) << 16);
}
// reconstruct fp32 pair from hi/lo bf16 words
__device__ __forceinline__ float2 unsplit2(uint32_t h, uint32_t l) {
    float2 a, b;
    a.x = __bfloat162float(__ushort_as_bfloat16((unsigned short)(h & 0xFFFF)));
    a.y = __bfloat162float(__ushort_as_bfloat16((unsigned short)(h >> 16)));
    b.x = __bfloat162float(__ushort_as_bfloat16((unsigned short)(l & 0xFFFF)));
    b.y = __bfloat162float(__ushort_as_bfloat16((unsigned short)(l >> 16)));
    return make_float2(a.x + b.x, a.y + b.y);
}

// ---------------- smem layout ----------------
#define TILE_B  (128 * STRB)              // 34816
#define SM_W2HI 0
#define SM_W2LO (1 * TILE_B)
#define SM_HHI  (2 * TILE_B)              // W1hi per depth, then H hi
#define SM_HLO  (3 * TILE_B)              // W1lo per depth, then H lo
#define SM_AHI  (4 * TILE_B)
#define SM_ALO  (5 * TILE_B)
#define SM_PIDX (6 * TILE_B)              // 128 B
#define SM_CPRE (6 * TILE_B + 128)        // 2048 B
#define SM_B2   (6 * TILE_B + 128 + 2048) // 512 B
#define SMEM_TOTAL (6 * TILE_B + 128 + 2048 + 512)

// single split-term for a 32x32 warp tile with double-buffered fragments
__device__ __forceinline__ void gemm_term(uint32_t Abase, uint32_t Bbase,
                                          int r0, int c0, int lane,
                                          float acc[2][4][4]) {
    const uint32_t rsel = (uint32_t)(lane & 15);
    const uint32_t ksel = (uint32_t)(lane >> 4) * 16;
    uint32_t aRow0 = Abase + (r0 + rsel) * STRB + ksel;
    uint32_t aRow1 = aRow0 + 16 * STRB;
    uint32_t bRow0 = Bbase + (c0 + rsel) * STRB + ksel;
    uint32_t bRow1 = bRow0 + 16 * STRB;
    uint32_t A0[2][4], A1[2][4], B0[2][4], B1[2][4];
    ldsm4(aRow0, A0[0]); ldsm4(aRow1, A1[0]);
    ldsm4(bRow0, B0[0]); ldsm4(bRow1, B1[0]);
#pragma unroll
    for (int kc = 0; kc < 8; kc++) {
        const int cur = kc & 1, nxt = cur ^ 1;
        if (kc < 7) {
            uint32_t kb = (kc + 1) * 32;
            ldsm4(aRow0 + kb, A0[nxt]); ldsm4(aRow1 + kb, A1[nxt]);
            ldsm4(bRow0 + kb, B0[nxt]); ldsm4(bRow1 + kb, B1[nxt]);
        }
        mma16816(acc[0][0], A0[cur], B0[cur][0], B0[cur][2]);
        mma16816(acc[0][1], A0[cur], B0[cur][1], B0[cur][3]);
        mma16816(acc[0][2], A0[cur], B1[cur][0], B1[cur][2]);
        mma16816(acc[0][3], A0[cur], B1[cur][1], B1[cur][3]);
        mma16816(acc[1][0], A1[cur], B0[cur][0], B0[cur][2]);
        mma16816(acc[1][1], A1[cur], B0[cur][1], B0[cur][3]);
        mma16816(acc[1][2], A1[cur], B1[cur][0], B1[cur][2]);
        mma16816(acc[1][3], A1[cur], B1[cur][1], B1[cur][3]);
    }
}

// ---------------- grid barrier (sense-reversing; even uses -> state restored) ----------------
__device__ __forceinline__ void grid_barrier(unsigned target) {
    __syncthreads();
    if (threadIdx.x == 0) {
        __threadfence();
        unsigned old = atomicAdd(&g_cnt, 1u);
        if (old == gridDim.x - 1) {
            g_cnt = 0;
            __threadfence();
            g_sense = target;
        } else {
            while (g_sense != target) __nanosleep(64);
        }
        __threadfence();
    }
    __syncthreads();
}

// ---------------- prep ----------------
__global__ void prep_kernel(const float* __restrict__ emb,
                            const float* __restrict__ W1,
                            const float* __restrict__ W2,
                            float* __restrict__ out) {
    int n = blockIdx.x, tid = threadIdx.x;  // 128 x 256
    for (int k = tid; k < 192; k += 256) {
        float v = W1[n * 192 + k];
        if (k < 128) {
            __nv_bfloat16 h = __float2bfloat16(v);
            g_w1hi[n * HID + k] = h;
            g_w1lo[n * HID + k] = __float2bfloat16(v - __bfloat162float(h));
        } else {
            g_W1bT[(k - 128) * HID + n] = v;
        }
    }
    for (int k = tid; k < 128; k += 256) {
        float v = W2[n * HID + k];
        __nv_bfloat16 h = __float2bfloat16(v);
        g_w2hi[n * HID + k] = h;
        g_w2lo[n * HID + k] = __float2bfloat16(v - __bfloat162float(h));
    }
    int g = n * 256 + tid;
    if (g < NB * HID) {
        int b = g >> 7, c = g & 127;
        out[(size_t)b * ROWS_PER_B * HID + c] = emb[g];
        g_buf[(size_t)b * HID + c] = emb[g];      // g_row 0 = root
    }
    // zero row ZROW: keep it zero every run (cheap, deterministic)
    if (n == 0) {
        float* zr = g_buf + (size_t)ZROW * NB * HID;
        for (int i = tid; i < NB * HID; i += 256) zr[i] = 0.f;
    }
}

// ---------------- c_pre = W1b @ ne + b1 ----------------
__global__ __launch_bounds__(256) void cpre_kernel(const float* __restrict__ emb_table,
                                                   const float* __restrict__ b1) {
    __shared__ float sne[32][64];
    __shared__ float sw[64][128];
    int tid = threadIdx.x;
    int row0 = blockIdx.x * 32;
    for (int i = tid; i < 32 * 64; i += 256) {
        int r = i >> 6, e = i & 63;
        sne[r][e] = emb_table[(size_t)(2 + row0 + r) * 64 + e];
    }
    for (int i = tid; i < 64 * 128; i += 256)
        sw[i >> 7][i & 127] = g_W1bT[i];
    __syncthreads();
    int c = tid & 127;
    int rh = (tid >> 7) * 16;
    float acc[16];
    float bv = b1[c];
#pragma unroll
    for (int rr = 0; rr < 16; rr++) acc[rr] = bv;
    for (int k = 0; k < 64; k++) {
        float w = sw[k][c];
#pragma unroll
        for (int rr = 0; rr < 16; rr++) acc[rr] += sne[rh + rr][k] * w;
    }
#pragma unroll
    for (int rr = 0; rr < 16; rr++)
        g_cpre[(size_t)(row0 + rh + rr) * HID + c] = acc[rr];
}

// ---------------- persistent DAG kernel: all 32 depths ----------------
__global__ __launch_bounds__(NTHREADS, 1)
void dag_kernel(float* __restrict__ out, const int* __restrict__ pidx,
                const float* __restrict__ b2) {
    extern __shared__ char smc[];
    const uint32_t sb = smem_u32(smc);
    const int tid = threadIdx.x;
    const int wid = tid >> 5, lane = tid & 31;
    const int n0 = blockIdx.x * 4;

    // one-time: W2 tiles + b2
    {
        const uint2* w2h = (const uint2*)g_w2hi;
        const uint2* w2l = (const uint2*)g_w2lo;
        for (int i = tid; i < 128 * 32; i += NTHREADS) {
            int r = i >> 5, q = i & 31;
            uint32_t off = (uint32_t)r * STRB + q * 8;
            *(uint2*)(smc + SM_W2HI + off) = w2h[i];
            *(uint2*)(smc + SM_W2LO + off) = w2l[i];
        }
        if (tid < 128) ((float*)(smc + SM_B2))[tid] = b2[tid];
    }

    for (int d = 0; d < DEPTH; d++) {
        // per-depth: W1 -> H region, pidx, cpre
        {
            const uint2* w1h = (const uint2*)g_w1hi;
            const uint2* w1l = (const uint2*)g_w1lo;
            for (int i = tid; i < 128 * 32; i += NTHREADS) {
                int r = i >> 5, q = i & 31;
                uint32_t off = (uint32_t)r * STRB + q * 8;
                *(uint2*)(smc + SM_HHI + off) = w1h[i];
                *(uint2*)(smc + SM_HLO + off) = w1l[i];
            }
            if (tid < 32)
                ((int*)(smc + SM_PIDX))[tid] =
                    pidx[(d * NODES + n0 + (tid >> 3)) * NPAR + (tid & 7)];
            float* s_cpre = (float*)(smc + SM_CPRE);
            const float* gc = g_cpre + (size_t)(d * NODES + n0) * HID;
            if (tid < 512) s_cpre[tid] = gc[tid];
        }
        __syncthreads();

        // ---- gather: branchless, per-warp parent pointers ----
        {
            const int* s_pidx = (const int*)(smc + SM_PIDX);
            const int nnw = wid >> 2;           // node handled by this warp
            const int bbase = (wid & 3) * 8;    // batch base
            const float* pb[NPAR];
#pragma unroll
            for (int p = 0; p < NPAR; p++) {
                int s = s_pidx[nnw * NPAR + p];
                int row = s ? (s - 1) : ZROW;
                pb[p] = g_buf + (size_t)row * (NB * HID) + lane * 4;
            }
#pragma unroll
            for (int rr = 0; rr < 8; rr++) {
                int b = bbase + rr;
                float x = 0.f, y = 0.f, z = 0.f, w = 0.f;
#pragma unroll
                for (int p = 0; p < NPAR; p++) {
                    float4 v = *(const float4*)(pb[p] + (size_t)b * HID);
                    x += v.x; y += v.y; z += v.z; w += v.w;
                }
                int r = nnw * 32 + b;           // tile row (== wid*8+rr)
                uint32_t h0, l0, h1, l1;
                split2(x, y, h0, l0);
                split2(z, w, h1, l1);
                uint32_t o = (uint32_t)r * STRB + lane * 8;
                *(uint32_t*)(smc + SM_AHI + o) = h0;
                *(uint32_t*)(smc + SM_AHI + o + 4) = h1;
                *(uint32_t*)(smc + SM_ALO + o) = l0;
                *(uint32_t*)(smc + SM_ALO + o + 4) = l1;
            }
        }
        __syncthreads();

        const int nn = wid & 3;           // epilogue/GEMM node = row group
        const int r0 = nn * 32;
        const int c0 = (wid >> 2) * 32;
        const int tq = lane >> 2;
        const int tc = (lane & 3) * 2;
        const float* s_cpre = (const float*)(smc + SM_CPRE);
        const float* s_b2 = (const float*)(smc + SM_B2);

        float acc[2][4][4];
#pragma unroll
        for (int mt = 0; mt < 2; mt++)
#pragma unroll
            for (int nt = 0; nt < 4; nt++)
#pragma unroll
                for (int q = 0; q < 4; q++) acc[mt][nt][q] = 0.f;

        // ---- GEMM1: A x W1 (W1 lives in H region) ----
        gemm_term(sb + SM_AHI, sb + SM_HHI, r0, c0, lane, acc);
        gemm_term(sb + SM_ALO, sb + SM_HHI, r0, c0, lane, acc);
        gemm_term(sb + SM_AHI, sb + SM_HLO, r0, c0, lane, acc);

        __syncthreads();  // everyone done reading W1 before H overwrite

        // ---- relu(D1 + cpre) -> split -> H region ----
#pragma unroll
        for (int mt = 0; mt < 2; mt++) {
#pragma unroll
            for (int nt = 0; nt < 4; nt++) {
                int c = c0 + nt * 8 + tc;
                float cp0 = s_cpre[nn * HID + c], cp1 = s_cpre[nn * HID + c + 1];
                float v0 = fmaxf(acc[mt][nt][0] + cp0, 0.f);
                float v1 = fmaxf(acc[mt][nt][1] + cp1, 0.f);
                float v2 = fmaxf(acc[mt][nt][2] + cp0, 0.f);
                float v3 = fmaxf(acc[mt][nt][3] + cp1, 0.f);
                uint32_t hi, lo;
                uint32_t oA = (uint32_t)(r0 + mt * 16 + tq) * STRB + c * 2;
                uint32_t oB = oA + 8 * STRB;
                split2(v0, v1, hi, lo);
                *(uint32_t*)(smc + SM_HHI + oA) = hi;
                *(uint32_t*)(smc + SM_HLO + oA) = lo;
                split2(v2, v3, hi, lo);
                *(uint32_t*)(smc + SM_HHI + oB) = hi;
                *(uint32_t*)(smc + SM_HLO + oB) = lo;
            }
        }
        __syncthreads();

#pragma unroll
        for (int mt = 0; mt < 2; mt++)
#pragma unroll
            for (int nt = 0; nt < 4; nt++)
#pragma unroll
                for (int q = 0; q < 4; q++) acc[mt][nt][q] = 0.f;

        // ---- GEMM2: H x W2 ----
        gemm_term(sb + SM_HHI, sb + SM_W2HI, r0, c0, lane, acc);
        gemm_term(sb + SM_HLO, sb + SM_W2HI, r0, c0, lane, acc);
        gemm_term(sb + SM_HHI, sb + SM_W2LO, r0, c0, lane, acc);

        // ---- epilogue: pv from A tiles (intact), out = pv + D2 + b2 ----
        {
            const int orow = 1 + d * NODES + n0 + nn;  // out row == g_buf row
#pragma unroll
            for (int mt = 0; mt < 2; mt++) {
#pragma unroll
                for (int half = 0; half < 2; half++) {
                    int b = mt * 16 + tq + half * 8;
                    int rA = r0 + b;
                    float* po = out + ((size_t)b * ROWS_PER_B + orow) * HID;
                    float* pg = g_buf + ((size_t)orow * NB + b) * HID;
#pragma unroll
                    for (int nt = 0; nt < 4; nt++) {
                        int c = c0 + nt * 8 + tc;
                        uint32_t off = (uint32_t)rA * STRB + c * 2;
                        float2 pv = unsplit2(*(const uint32_t*)(smc + SM_AHI + off),
                                             *(const uint32_t*)(smc + SM_ALO + off));
                        float2 o;
                        o.x = acc[mt][nt][half * 2 + 0] + s_b2[c] + pv.x;
                        o.y = acc[mt][nt][half * 2 + 1] + s_b2[c + 1] + pv.y;
                        *(float2*)(po + c) = o;
                        *(float2*)(pg + c) = o;
                    }
                }
            }
        }

        grid_barrier((unsigned)((d & 1) ^ 1));   // 1,0,1,0,... ends at 0
    }
}

extern "C" void kernel_launch(void* const* d_in, const int* in_sizes, int n_in,
                              void* d_out, int out_size) {
    const float* embedding  = (const float*)d_in[0];
    const float* emb_table  = (const float*)d_in[1];
    const float* W1         = (const float*)d_in[2];
    const float* b1         = (const float*)d_in[3];
    const float* W2         = (const float*)d_in[4];
    const float* b2         = (const float*)d_in[5];
    const int*   parent_idx = (const int*)d_in[6];
    float* out = (float*)d_out;
    (void)in_sizes; (void)n_in; (void)out_size;

    cudaFuncSetAttribute(dag_kernel,
                         cudaFuncAttributeMaxDynamicSharedMemorySize, SMEM_TOTAL);

    prep_kernel<<<128, 256>>>(embedding, W1, W2, out);
    cpre_kernel<<<DEPTH * NODES / 32, 256>>>(emb_table, b1);
    dag_kernel<<<128, NTHREADS, SMEM_TOTAL>>>(out, parent_idx, b2);
}

// round 7
// speedup vs baseline: 2.1332x; 1.4222x over previous
#include <cuda_runtime.h>
#include <cuda_bf16.h>
#include <cstdint>

#define DEPTH 32
#define NODES 512
#define NPAR 8
#define NB 32
#define HID 128
#define ROWS_PER_B 16385
#define STRB 272            // smem tile row stride bytes (136 bf16)
#define NTHREADS 512
#define ZROW 16385          // permanent zero row of g_buf (slot 0 padding)

// ---------------- device statics ----------------
__device__ float g_cpre[DEPTH * NODES * HID];
__device__ float g_W1bT[64 * HID];
__device__ __nv_bfloat16 g_w1hi[HID * HID], g_w1lo[HID * HID];  // [n][k]
__device__ __nv_bfloat16 g_w2hi[HID * HID], g_w2lo[HID * HID];  // [n][k]
// node-major value mirror + 1 zero row: g_buf[g_row][batch][128], g_row = slot-1
__device__ float g_buf[(size_t)(2 + DEPTH * NODES) * NB * HID];
// grid barrier state (restored to 0 after 32 (even) barriers per run)
__device__ unsigned g_cnt;
__device__ volatile unsigned g_sense;

// ---------------- helpers ----------------
__device__ __forceinline__ uint32_t smem_u32(const void* p) {
    uint32_t a;
    asm("{ .reg .u64 t; cvta.to.shared.u64 t, %1; cvt.u32.u64 %0, t; }" : "=r"(a) : "l"(p));
    return a;
}
__device__ __forceinline__ void ldsm4(uint32_t addr, uint32_t r[4]) {
    asm volatile("ldmatrix.sync.aligned.m8n8.x4.shared.b16 {%0,%1,%2,%3}, [%4];"
        : "=r"(r[0]), "=r"(r[1]), "=r"(r[2]), "=r"(r[3]) : "r"(addr));
}
__device__ __forceinline__ void mma16816(float c[4], const uint32_t a[4],
                                         uint32_t b0, uint32_t b1) {
    asm volatile("mma.sync.aligned.m16n8k16.row.col.f32.bf16.bf16.f32 "
        "{%0,%1,%2,%3}, {%4,%5,%6,%7}, {%8,%9}, {%0,%1,%2,%3};"
        : "+f"(c[0]), "+f"(c[1]), "+f"(c[2]), "+f"(c[3])
        : "r"(a[0]), "r"(a[1]), "r"(a[2]), "r"(a[3]), "r"(b0), "r"(b1));
}
__device__ __forceinline__ void split2(float a, float b, uint32_t& hi, uint32_t& lo) {
    __nv_bfloat16 ah = __float2bfloat16(a), bh = __float2bfloat16(b);
    __nv_bfloat16 al = __float2bfloat16(a - __bfloat162float(ah));
    __nv_bfloat16 bl = __float2bfloat16(b - __bfloat162float(bh));
    hi = (uint32_t)__bfloat16_as_ushort(ah) | ((uint32_t)__bfloat16_as_ushort(bh) << 16);
    lo = (uint32_t)__bfloat16_as_ushort(al) | ((uint32_t)__bfloat16_as_ushort(bl) << 16);
}
__device__ __forceinline__ float2 unsplit2(uint32_t h, uint32_t l) {
    float ax = __bfloat162float(__ushort_as_bfloat16((unsigned short)(h & 0xFFFF)));
    float ay = __bfloat162float(__ushort_as_bfloat16((unsigned short)(h >> 16)));
    float bx = __bfloat162float(__ushort_as_bfloat16((unsigned short)(l & 0xFFFF)));
    float by = __bfloat162float(__ushort_as_bfloat16((unsigned short)(l >> 16)));
    return make_float2(ax + bx, ay + by);
}

// ---------------- smem layout ----------------
#define TILE_B  (128 * STRB)              // 34816
#define SM_W2HI 0
#define SM_W2LO (1 * TILE_B)
#define SM_HHI  (2 * TILE_B)              // W1hi (prefetched), then H hi
#define SM_HLO  (3 * TILE_B)              // W1lo (prefetched), then H lo
#define SM_AHI  (4 * TILE_B)
#define SM_ALO  (5 * TILE_B)
#define SM_PIDX (6 * TILE_B)              // 128 B
#define SM_CPRE (6 * TILE_B + 128)        // 2048 B
#define SM_B2   (6 * TILE_B + 128 + 2048) // 512 B
#define SMEM_TOTAL (6 * TILE_B + 128 + 2048 + 512)

// fused 3-term split GEMM for a 32x32 warp tile:
// acc += Ahi*Bhi + Alo*Bhi + Ahi*Blo  (K=128)
__device__ __forceinline__ void gemm3(uint32_t AhiB, uint32_t AloB,
                                      uint32_t BhiB, uint32_t BloB,
                                      int r0, int c0, int lane,
                                      float acc[2][4][4]) {
    const uint32_t rsel = (uint32_t)(lane & 15);
    const uint32_t ksel = (uint32_t)(lane >> 4) * 16;
    const uint32_t aoff = (r0 + rsel) * STRB + ksel;
    const uint32_t boff = (c0 + rsel) * STRB + ksel;
    uint32_t ah0 = AhiB + aoff, ah1 = ah0 + 16 * STRB;
    uint32_t al0 = AloB + aoff, al1 = al0 + 16 * STRB;
    uint32_t bh0 = BhiB + boff, bh1 = bh0 + 16 * STRB;
    uint32_t bl0 = BloB + boff, bl1 = bl0 + 16 * STRB;
#pragma unroll
    for (int kc = 0; kc < 8; kc++) {
        const uint32_t kb = kc * 32;
        uint32_t Ah0[4], Ah1[4], Al0[4], Al1[4];
        uint32_t Bh0[4], Bh1[4], Bl0[4], Bl1[4];
        ldsm4(ah0 + kb, Ah0); ldsm4(ah1 + kb, Ah1);
        ldsm4(bh0 + kb, Bh0); ldsm4(bh1 + kb, Bh1);
        ldsm4(al0 + kb, Al0); ldsm4(al1 + kb, Al1);
        ldsm4(bl0 + kb, Bl0); ldsm4(bl1 + kb, Bl1);
        // term Ahi x Bhi
        mma16816(acc[0][0], Ah0, Bh0[0], Bh0[2]);
        mma16816(acc[0][1], Ah0, Bh0[1], Bh0[3]);
        mma16816(acc[0][2], Ah0, Bh1[0], Bh1[2]);
        mma16816(acc[0][3], Ah0, Bh1[1], Bh1[3]);
        mma16816(acc[1][0], Ah1, Bh0[0], Bh0[2]);
        mma16816(acc[1][1], Ah1, Bh0[1], Bh0[3]);
        mma16816(acc[1][2], Ah1, Bh1[0], Bh1[2]);
        mma16816(acc[1][3], Ah1, Bh1[1], Bh1[3]);
        // term Alo x Bhi
        mma16816(acc[0][0], Al0, Bh0[0], Bh0[2]);
        mma16816(acc[0][1], Al0, Bh0[1], Bh0[3]);
        mma16816(acc[0][2], Al0, Bh1[0], Bh1[2]);
        mma16816(acc[0][3], Al0, Bh1[1], Bh1[3]);
        mma16816(acc[1][0], Al1, Bh0[0], Bh0[2]);
        mma16816(acc[1][1], Al1, Bh0[1], Bh0[3]);
        mma16816(acc[1][2], Al1, Bh1[0], Bh1[2]);
        mma16816(acc[1][3], Al1, Bh1[1], Bh1[3]);
        // term Ahi x Blo
        mma16816(acc[0][0], Ah0, Bl0[0], Bl0[2]);
        mma16816(acc[0][1], Ah0, Bl0[1], Bl0[3]);
        mma16816(acc[0][2], Ah0, Bl1[0], Bl1[2]);
        mma16816(acc[0][3], Ah0, Bl1[1], Bl1[3]);
        mma16816(acc[1][0], Ah1, Bl0[0], Bl0[2]);
        mma16816(acc[1][1], Ah1, Bl0[1], Bl0[3]);
        mma16816(acc[1][2], Ah1, Bl1[0], Bl1[2]);
        mma16816(acc[1][3], Ah1, Bl1[1], Bl1[3]);
    }
}

// ---------------- prep ----------------
__global__ void prep_kernel(const float* __restrict__ emb,
                            const float* __restrict__ W1,
                            const float* __restrict__ W2,
                            float* __restrict__ out) {
    int n = blockIdx.x, tid = threadIdx.x;  // 128 x 256
    for (int k = tid; k < 192; k += 256) {
        float v = W1[n * 192 + k];
        if (k < 128) {
            __nv_bfloat16 h = __float2bfloat16(v);
            g_w1hi[n * HID + k] = h;
            g_w1lo[n * HID + k] = __float2bfloat16(v - __bfloat162float(h));
        } else {
            g_W1bT[(k - 128) * HID + n] = v;
        }
    }
    for (int k = tid; k < 128; k += 256) {
        float v = W2[n * HID + k];
        __nv_bfloat16 h = __float2bfloat16(v);
        g_w2hi[n * HID + k] = h;
        g_w2lo[n * HID + k] = __float2bfloat16(v - __bfloat162float(h));
    }
    int g = n * 256 + tid;
    if (g < NB * HID) {
        int b = g >> 7, c = g & 127;
        out[(size_t)b * ROWS_PER_B * HID + c] = emb[g];
        g_buf[(size_t)b * HID + c] = emb[g];      // g_row 0 = root
    }
    if (n == 0) {
        float* zr = g_buf + (size_t)ZROW * NB * HID;
        for (int i = tid; i < NB * HID; i += 256) zr[i] = 0.f;
    }
}

// ---------------- c_pre = W1b @ ne + b1 ----------------
__global__ __launch_bounds__(256) void cpre_kernel(const float* __restrict__ emb_table,
                                                   const float* __restrict__ b1) {
    __shared__ float sne[32][64];
    __shared__ float sw[64][128];
    int tid = threadIdx.x;
    int row0 = blockIdx.x * 32;
    for (int i = tid; i < 32 * 64; i += 256) {
        int r = i >> 6, e = i & 63;
        sne[r][e] = emb_table[(size_t)(2 + row0 + r) * 64 + e];
    }
    for (int i = tid; i < 64 * 128; i += 256)
        sw[i >> 7][i & 127] = g_W1bT[i];
    __syncthreads();
    int c = tid & 127;
    int rh = (tid >> 7) * 16;
    float acc[16];
    float bv = b1[c];
#pragma unroll
    for (int rr = 0; rr < 16; rr++) acc[rr] = bv;
    for (int k = 0; k < 64; k++) {
        float w = sw[k][c];
#pragma unroll
        for (int rr = 0; rr < 16; rr++) acc[rr] += sne[rh + rr][k] * w;
    }
#pragma unroll
    for (int rr = 0; rr < 16; rr++)
        g_cpre[(size_t)(row0 + rh + rr) * HID + c] = acc[rr];
}

// per-depth CTA-local prefetch: W1 -> H region, pidx, cpre
__device__ __forceinline__ void prefetch_depth(char* smc, const int* __restrict__ pidx,
                                               int d, int n0, int tid) {
    const uint2* w1h = (const uint2*)g_w1hi;
    const uint2* w1l = (const uint2*)g_w1lo;
    for (int i = tid; i < 128 * 32; i += NTHREADS) {
        int r = i >> 5, q = i & 31;
        uint32_t off = (uint32_t)r * STRB + q * 8;
        *(uint2*)(smc + SM_HHI + off) = w1h[i];
        *(uint2*)(smc + SM_HLO + off) = w1l[i];
    }
    if (tid < 32)
        ((int*)(smc + SM_PIDX))[tid] =
            pidx[(d * NODES + n0 + (tid >> 3)) * NPAR + (tid & 7)];
    float* s_cpre = (float*)(smc + SM_CPRE);
    const float* gc = g_cpre + (size_t)(d * NODES + n0) * HID;
    if (tid < 512) s_cpre[tid] = gc[tid];
}

// ---------------- persistent DAG kernel ----------------
__global__ __launch_bounds__(NTHREADS, 1)
void dag_kernel(float* __restrict__ out, const int* __restrict__ pidx,
                const float* __restrict__ b2) {
    extern __shared__ char smc[];
    const uint32_t sb = smem_u32(smc);
    const int tid = threadIdx.x;
    const int wid = tid >> 5, lane = tid & 31;
    const int n0 = blockIdx.x * 4;

    // one-time: W2 tiles + b2 + depth-0 prefetch
    {
        const uint2* w2h = (const uint2*)g_w2hi;
        const uint2* w2l = (const uint2*)g_w2lo;
        for (int i = tid; i < 128 * 32; i += NTHREADS) {
            int r = i >> 5, q = i & 31;
            uint32_t off = (uint32_t)r * STRB + q * 8;
            *(uint2*)(smc + SM_W2HI + off) = w2h[i];
            *(uint2*)(smc + SM_W2LO + off) = w2l[i];
        }
        if (tid < 128) ((float*)(smc + SM_B2))[tid] = b2[tid];
        prefetch_depth(smc, pidx, 0, n0, tid);
    }
    __syncthreads();

    for (int d = 0; d < DEPTH; d++) {
        // ---- gather: branchless, per-warp parent pointers ----
        {
            const int* s_pidx = (const int*)(smc + SM_PIDX);
            const int nnw = wid >> 2;           // node handled by this warp
            const int bbase = (wid & 3) * 8;    // batch base
            const float* pb[NPAR];
#pragma unroll
            for (int p = 0; p < NPAR; p++) {
                int s = s_pidx[nnw * NPAR + p];
                int row = s ? (s - 1) : ZROW;
                pb[p] = g_buf + (size_t)row * (NB * HID) + lane * 4;
            }
#pragma unroll
            for (int rr = 0; rr < 8; rr++) {
                int b = bbase + rr;
                float x = 0.f, y = 0.f, z = 0.f, w = 0.f;
#pragma unroll
                for (int p = 0; p < NPAR; p++) {
                    float4 v = *(const float4*)(pb[p] + (size_t)b * HID);
                    x += v.x; y += v.y; z += v.z; w += v.w;
                }
                int r = nnw * 32 + b;
                uint32_t h0, l0, h1, l1;
                split2(x, y, h0, l0);
                split2(z, w, h1, l1);
                uint32_t o = (uint32_t)r * STRB + lane * 8;
                *(uint32_t*)(smc + SM_AHI + o) = h0;
                *(uint32_t*)(smc + SM_AHI + o + 4) = h1;
                *(uint32_t*)(smc + SM_ALO + o) = l0;
                *(uint32_t*)(smc + SM_ALO + o + 4) = l1;
            }
        }
        __syncthreads();

        const int nn = wid & 3;
        const int r0 = nn * 32;
        const int c0 = (wid >> 2) * 32;
        const int tq = lane >> 2;
        const int tc = (lane & 3) * 2;
        const float* s_cpre = (const float*)(smc + SM_CPRE);
        const float* s_b2 = (const float*)(smc + SM_B2);

        float acc[2][4][4];
#pragma unroll
        for (int mt = 0; mt < 2; mt++)
#pragma unroll
            for (int nt = 0; nt < 4; nt++)
#pragma unroll
                for (int q = 0; q < 4; q++) acc[mt][nt][q] = 0.f;

        // ---- GEMM1 (fused 3 terms): A x W1 (W1 in H region) ----
        gemm3(sb + SM_AHI, sb + SM_ALO, sb + SM_HHI, sb + SM_HLO, r0, c0, lane, acc);
        __syncthreads();  // everyone done reading W1 before H overwrite

        // ---- relu(D1 + cpre) -> split -> H region ----
#pragma unroll
        for (int mt = 0; mt < 2; mt++) {
#pragma unroll
            for (int nt = 0; nt < 4; nt++) {
                int c = c0 + nt * 8 + tc;
                float cp0 = s_cpre[nn * HID + c], cp1 = s_cpre[nn * HID + c + 1];
                float v0 = fmaxf(acc[mt][nt][0] + cp0, 0.f);
                float v1 = fmaxf(acc[mt][nt][1] + cp1, 0.f);
                float v2 = fmaxf(acc[mt][nt][2] + cp0, 0.f);
                float v3 = fmaxf(acc[mt][nt][3] + cp1, 0.f);
                uint32_t hi, lo;
                uint32_t oA = (uint32_t)(r0 + mt * 16 + tq) * STRB + c * 2;
                uint32_t oB = oA + 8 * STRB;
                split2(v0, v1, hi, lo);
                *(uint32_t*)(smc + SM_HHI + oA) = hi;
                *(uint32_t*)(smc + SM_HLO + oA) = lo;
                split2(v2, v3, hi, lo);
                *(uint32_t*)(smc + SM_HHI + oB) = hi;
                *(uint32_t*)(smc + SM_HLO + oB) = lo;
            }
        }
        __syncthreads();

#pragma unroll
        for (int mt = 0; mt < 2; mt++)
#pragma unroll
            for (int nt = 0; nt < 4; nt++)
#pragma unroll
                for (int q = 0; q < 4; q++) acc[mt][nt][q] = 0.f;

        // ---- GEMM2 (fused 3 terms): H x W2 ----
        gemm3(sb + SM_HHI, sb + SM_HLO, sb + SM_W2HI, sb + SM_W2LO, r0, c0, lane, acc);

        // ---- epilogue: pv from A tiles, out = pv + D2 + b2 ----
        {
            const int orow = 1 + d * NODES + n0 + nn;  // out row == g_buf row
#pragma unroll
            for (int mt = 0; mt < 2; mt++) {
#pragma unroll
                for (int half = 0; half < 2; half++) {
                    int b = mt * 16 + tq + half * 8;
                    int rA = r0 + b;
                    float* po = out + ((size_t)b * ROWS_PER_B + orow) * HID;
                    float* pg = g_buf + ((size_t)orow * NB + b) * HID;
#pragma unroll
                    for (int nt = 0; nt < 4; nt++) {
                        int c = c0 + nt * 8 + tc;
                        uint32_t off = (uint32_t)rA * STRB + c * 2;
                        float2 pv = unsplit2(*(const uint32_t*)(smc + SM_AHI + off),
                                             *(const uint32_t*)(smc + SM_ALO + off));
                        float2 o;
                        o.x = acc[mt][nt][half * 2 + 0] + s_b2[c] + pv.x;
                        o.y = acc[mt][nt][half * 2 + 1] + s_b2[c + 1] + pv.y;
                        *(float2*)(po + c) = o;
                        *(float2*)(pg + c) = o;
                    }
                }
            }
        }
        __syncthreads();   // all g_buf/out stores issued; H (W1') safe to overwrite

        // ---- arrive, prefetch next depth (hides barrier latency), wait ----
        const unsigned target = (unsigned)((d & 1) ^ 1);
        if (tid == 0) {
            __threadfence();
            unsigned old = atomicAdd(&g_cnt, 1u);
            if (old == gridDim.x - 1) {
                g_cnt = 0;
                __threadfence();
                g_sense = target;
            }
        }
        if (d + 1 < DEPTH)
            prefetch_depth(smc, pidx, d + 1, n0, tid);
        if (tid == 0) {
            while (g_sense != target) __nanosleep(32);
            __threadfence();
        }
        __syncthreads();
    }
}

extern "C" void kernel_launch(void* const* d_in, const int* in_sizes, int n_in,
                              void* d_out, int out_size) {
    const float* embedding  = (const float*)d_in[0];
    const float* emb_table  = (const float*)d_in[1];
    const float* W1         = (const float*)d_in[2];
    const float* b1         = (const float*)d_in[3];
    const float* W2         = (const float*)d_in[4];
    const float* b2         = (const float*)d_in[5];
    const int*   parent_idx = (const int*)d_in[6];
    float* out = (float*)d_out;
    (void)in_sizes; (void)n_in; (void)out_size;

    cudaFuncSetAttribute(dag_kernel,
                         cudaFuncAttributeMaxDynamicSharedMemorySize, SMEM_TOTAL);

    prep_kernel<<<128, 256>>>(embedding, W1, W2, out);
    cpre_kernel<<<DEPTH * NODES / 32, 256>>>(emb_table, b1);
    dag_kernel<<<128, NTHREADS, SMEM_TOTAL>>>(out, parent_idx, b2);
}